// round 1
// baseline (speedup 1.0000x reference)
#include <cuda_runtime.h>
#include <math.h>

#define NNODES 8192
#define DIM    512
#define NLAYER 2

// -------- scratch (no allocations allowed -> __device__ globals) --------
__device__ float g_Wh[NNODES * DIM];                 // 16 MB
__device__ float g_Ws[NNODES * DIM];                 // 16 MB
__device__ float g_X [NNODES * DIM];                 // 16 MB (inter-layer activations)
__device__ float g_S [(size_t)NNODES * NNODES];      // 256 MB score / prob matrix

__device__ __forceinline__ float lrelu(float v) { return v > 0.f ? v : 0.01f * v; }

// ---------------------------------------------------------------------------
// Classic 128x128x8 register-tiled fp32 SGEMM.
//   C[M,Ncols] = A[M,K] @ B            (TRANSB=false: B is [K,Ncols] row-major)
//                A[M,K] @ B^T          (TRANSB=true : B is [Ncols,K] row-major)
//   EPI=true: C = leaky_relu(C + R)    (R same layout as C)
// All dims assumed multiples of 128 / 8 (true here: 512, 1024, 8192).
// ---------------------------------------------------------------------------
template<bool TRANSB, bool EPI>
__global__ __launch_bounds__(256, 2)
void sgemm128(const float* __restrict__ A, int lda,
              const float* __restrict__ B, int ldb,
              float* __restrict__ C, int ldc,
              const float* __restrict__ R,
              int K)
{
    __shared__ float As[8][128];
    __shared__ float Bs[8][128];

    const int tid = threadIdx.x;
    const int m0 = blockIdx.y * 128;
    const int n0 = blockIdx.x * 128;
    const int tx = tid & 15;     // 16 col-groups
    const int ty = tid >> 4;     // 16 row-groups

    // A (and B when TRANSB) tile load: one float4 per thread, transposed into smem
    const int lrow = tid >> 1;           // 0..127
    const int lk   = (tid & 1) << 2;     // 0 or 4
    // B tile load (NN): one float4 per thread, direct
    const int bkr  = tid >> 5;           // 0..7
    const int bnc  = (tid & 31) << 2;    // 0..124

    float acc[8][8];
#pragma unroll
    for (int i = 0; i < 8; i++)
#pragma unroll
        for (int j = 0; j < 8; j++) acc[i][j] = 0.f;

    const float* Aptr = A + (size_t)(m0 + lrow) * lda + lk;
    const float* Bptr = TRANSB ? (B + (size_t)(n0 + lrow) * ldb + lk)
                               : (B + (size_t)bkr * ldb + n0 + bnc);

    for (int k0 = 0; k0 < K; k0 += 8) {
        float4 av = *(const float4*)(Aptr + k0);
        As[lk + 0][lrow] = av.x; As[lk + 1][lrow] = av.y;
        As[lk + 2][lrow] = av.z; As[lk + 3][lrow] = av.w;
        if (TRANSB) {
            float4 bv = *(const float4*)(Bptr + k0);
            Bs[lk + 0][lrow] = bv.x; Bs[lk + 1][lrow] = bv.y;
            Bs[lk + 2][lrow] = bv.z; Bs[lk + 3][lrow] = bv.w;
        } else {
            float4 bv = *(const float4*)(Bptr + (size_t)k0 * ldb);
            *(float4*)&Bs[bkr][bnc] = bv;
        }
        __syncthreads();

#pragma unroll
        for (int kk = 0; kk < 8; kk++) {
            float a[8], b[8];
            *(float4*)&a[0] = *(const float4*)&As[kk][ty * 8];
            *(float4*)&a[4] = *(const float4*)&As[kk][ty * 8 + 4];
            *(float4*)&b[0] = *(const float4*)&Bs[kk][tx * 8];
            *(float4*)&b[4] = *(const float4*)&Bs[kk][tx * 8 + 4];
#pragma unroll
            for (int i = 0; i < 8; i++)
#pragma unroll
                for (int j = 0; j < 8; j++)
                    acc[i][j] = fmaf(a[i], b[j], acc[i][j]);
        }
        __syncthreads();
    }

#pragma unroll
    for (int i = 0; i < 8; i++) {
        const int row = m0 + ty * 8 + i;
        float* cp = C + (size_t)row * ldc + n0 + tx * 8;
        float4 v0 = make_float4(acc[i][0], acc[i][1], acc[i][2], acc[i][3]);
        float4 v1 = make_float4(acc[i][4], acc[i][5], acc[i][6], acc[i][7]);
        if (EPI) {
            const float* rp = R + (size_t)row * ldc + n0 + tx * 8;
            float4 r0 = *(const float4*)rp;
            float4 r1 = *(const float4*)(rp + 4);
            v0.x = lrelu(v0.x + r0.x); v0.y = lrelu(v0.y + r0.y);
            v0.z = lrelu(v0.z + r0.z); v0.w = lrelu(v0.w + r0.w);
            v1.x = lrelu(v1.x + r1.x); v1.y = lrelu(v1.y + r1.y);
            v1.z = lrelu(v1.z + r1.z); v1.w = lrelu(v1.w + r1.w);
        }
        *(float4*)cp = v0;
        *(float4*)(cp + 4) = v1;
    }
}

// ---------------------------------------------------------------------------
// Row softmax over S (in place), then multiply by adj (post-softmax mask).
// One block of 256 threads per row; row staged in smem (32 KB).
// ---------------------------------------------------------------------------
__global__ __launch_bounds__(256)
void softmax_mask_kernel(float* __restrict__ S, const float* __restrict__ adj)
{
    __shared__ float row[NNODES];
    __shared__ float red[256];
    const int tid = threadIdx.x;
    const size_t base = (size_t)blockIdx.x * NNODES;

    for (int j = tid * 4; j < NNODES; j += 1024)
        *(float4*)&row[j] = *(const float4*)&S[base + j];
    __syncthreads();

    float m = -INFINITY;
    for (int j = tid; j < NNODES; j += 256) m = fmaxf(m, row[j]);
    red[tid] = m; __syncthreads();
    for (int s = 128; s > 0; s >>= 1) {
        if (tid < s) red[tid] = fmaxf(red[tid], red[tid + s]);
        __syncthreads();
    }
    m = red[0]; __syncthreads();

    float l = 0.f;
    for (int j = tid; j < NNODES; j += 256) l += __expf(row[j] - m);
    red[tid] = l; __syncthreads();
    for (int s = 128; s > 0; s >>= 1) {
        if (tid < s) red[tid] += red[tid + s];
        __syncthreads();
    }
    const float inv = 1.0f / red[0];

    for (int j = tid * 4; j < NNODES; j += 1024) {
        float4 a = *(const float4*)&adj[base + j];
        float4 v;
        v.x = __expf(row[j + 0] - m) * inv * a.x;
        v.y = __expf(row[j + 1] - m) * inv * a.y;
        v.z = __expf(row[j + 2] - m) * inv * a.z;
        v.w = __expf(row[j + 3] - m) * inv * a.w;
        *(float4*)&S[base + j] = v;
    }
}

// ---------------------------------------------------------------------------
extern "C" void kernel_launch(void* const* d_in, const int* in_sizes, int n_in,
                              void* d_out, int out_size)
{
    const float* x0  = nullptr;
    const float* adj = nullptr;
    const float* W   = nullptr;
    for (int i = 0; i < n_in; i++) {
        const int s = in_sizes[i];
        if      (s == NNODES * DIM)                x0  = (const float*)d_in[i];
        else if (s == NNODES * NNODES / 1)         ; // handled below (too big for int? 67108864 fits)
        if      (s == 67108864)                    adj = (const float*)d_in[i];
        else if (s == NLAYER * DIM * 2 * DIM)      W   = (const float*)d_in[i];
    }

    float *Wh, *Ws, *Xb, *S;
    cudaGetSymbolAddress((void**)&Wh, g_Wh);
    cudaGetSymbolAddress((void**)&Ws, g_Ws);
    cudaGetSymbolAddress((void**)&Xb, g_X);
    cudaGetSymbolAddress((void**)&S,  g_S);

    const dim3 blk(256);
    const dim3 gProj (DIM    / 128, NNODES / 128);   // (4, 64)
    const dim3 gScore(NNODES / 128, NNODES / 128);   // (64, 64)
    const dim3 gOut  (DIM    / 128, NNODES / 128);   // (4, 64)

    const float* xin = x0;
    for (int l = 0; l < NLAYER; l++) {
        const float* Wl = W + (size_t)l * DIM * (2 * DIM);

        // proj: Wh = x @ W[:, :512],  Ws = x @ W[:, 512:]
        sgemm128<false, false><<<gProj, blk>>>(xin, DIM, Wl,       2 * DIM, Wh, DIM, nullptr, DIM);
        sgemm128<false, false><<<gProj, blk>>>(xin, DIM, Wl + DIM, 2 * DIM, Ws, DIM, nullptr, DIM);

        // scores: S = Wh @ Ws^T
        sgemm128<true, false><<<gScore, blk>>>(Wh, DIM, Ws, DIM, S, NNODES, nullptr, DIM);

        // P = softmax(S, axis=-1) * adj   (in place)
        softmax_mask_kernel<<<NNODES, blk>>>(S, adj);

        // out = leaky_relu(P @ Wh + xin)
        float* outp = (l == NLAYER - 1) ? (float*)d_out : Xb;
        sgemm128<false, true><<<gOut, blk>>>(S, NNODES, Wh, DIM, outp, DIM, xin, NNODES);
        xin = outp;
    }
}

// round 4
// speedup vs baseline: 2.0852x; 2.0852x over previous
#include <cuda_runtime.h>
#include <cuda_bf16.h>
#include <math.h>
#include <stdint.h>

#define NN 8192
#define DD 512
#define NL 2

// ---------------- device scratch (no allocations allowed) ----------------
__device__ float          g_S   [(size_t)NN * NN];        // 256 MB scores
__device__ __nv_bfloat16  g_Phi [(size_t)NN * NN];        // 128 MB
__device__ __nv_bfloat16  g_Plo [(size_t)NN * NN];        // 128 MB
__device__ float          g_proj[(size_t)NN * 2 * DD];    // 32 MB
__device__ float          g_Xf  [(size_t)NN * DD];        // 16 MB layer-0 output
__device__ __nv_bfloat16  g_Whhi[NN * DD], g_Whlo[NN * DD];
__device__ __nv_bfloat16  g_Wshi[NN * DD], g_Wslo[NN * DD];
__device__ __nv_bfloat16  g_WhThi[NN * DD], g_WhTlo[NN * DD];   // [512, 8192]
__device__ __nv_bfloat16  g_Xhi [NN * DD], g_Xlo [NN * DD];
__device__ __nv_bfloat16  g_Wthi[NL * 2 * DD * DD], g_Wtlo[NL * 2 * DD * DD]; // [L,1024,512]

// ---------------- PTX helpers (sm_80+ baseline only; NO tcgen05) ----------------
__device__ __forceinline__ uint32_t smem_u32(const void* p) {
    uint32_t a;
    asm("{ .reg .u64 t; cvta.to.shared.u64 t, %1; cvt.u32.u64 %0, t; }" : "=r"(a) : "l"(p));
    return a;
}
#define CP16(dst, src)  asm volatile("cp.async.cg.shared.global [%0], [%1], 16;" :: "r"(dst), "l"(src))
#define CP_COMMIT()     asm volatile("cp.async.commit_group;" ::: "memory")
#define CP_WAIT1()      asm volatile("cp.async.wait_group 1;" ::: "memory")

#define LDSM4(r, a) \
    asm volatile("ldmatrix.sync.aligned.m8n8.x4.shared.b16 {%0,%1,%2,%3}, [%4];" \
        : "=r"((r)[0]), "=r"((r)[1]), "=r"((r)[2]), "=r"((r)[3]) : "r"(a))
#define LDSM2(r, a) \
    asm volatile("ldmatrix.sync.aligned.m8n8.x2.shared.b16 {%0,%1}, [%2];" \
        : "=r"((r)[0]), "=r"((r)[1]) : "r"(a))

#define MMA16816(c, a, b) \
    asm volatile("mma.sync.aligned.m16n8k16.row.col.f32.bf16.bf16.f32 " \
        "{%0,%1,%2,%3}, {%4,%5,%6,%7}, {%8,%9}, {%0,%1,%2,%3};" \
        : "+f"((c)[0]), "+f"((c)[1]), "+f"((c)[2]), "+f"((c)[3]) \
        : "r"((a)[0]), "r"((a)[1]), "r"((a)[2]), "r"((a)[3]), "r"((b)[0]), "r"((b)[1]))

__device__ __forceinline__ float lrelu(float v) { return v > 0.f ? v : 0.01f * v; }

// ---------------------------------------------------------------------------
// bf16-split GEMM on HMMA (mma.sync m16n8k16):
//   C[M,N] = sum_K (Ahi+Alo)[M,K] * (Bhi+Blo)[N,K]^T   (3 terms: A0B0+A0B1+A1B0)
// BM=BN=128, BK=32. 8 warps (2x4), warp tile 64x32. 3-stage cp.async pipeline.
// Stage layout: 4 matrices (Ahi,Alo,Bhi,Blo), each 128 rows x 80B pitch.
// EPI: C = leaky_relu(C + R).
// ---------------------------------------------------------------------------
#define PITCH      80
#define MAT_BYTES  (128 * PITCH)       // 10240
#define STAGE_B    (4 * MAT_BYTES)     // 40960
#define GEMM_SMEM  (3 * STAGE_B)       // 122880

template<bool EPI>
__global__ void __launch_bounds__(256, 1)
gemm_mma(const __nv_bfloat16* __restrict__ Ahi, const __nv_bfloat16* __restrict__ Alo, int lda,
         const __nv_bfloat16* __restrict__ Bhi, const __nv_bfloat16* __restrict__ Blo, int ldb,
         float* __restrict__ C, int ldc, const float* __restrict__ R, int K)
{
    extern __shared__ char smem[];
    const uint32_t sb = smem_u32(smem);
    const int tid = threadIdx.x, wid = tid >> 5, lane = tid & 31;
    const int m0 = blockIdx.y * 128, n0 = blockIdx.x * 128;
    const int wm = (wid & 1) * 64;       // warp M offset
    const int wn = (wid >> 1) * 32;      // warp N offset
    const int NC = K >> 5;               // number of BK=32 chunks

    float acc[16][4];
#pragma unroll
    for (int i = 0; i < 16; i++)
#pragma unroll
        for (int q = 0; q < 4; q++) acc[i][q] = 0.f;

    // ---- load geometry: per matrix 512 x 16B chunks; thread loads 32B of one row
    const int lr = tid >> 1;               // row 0..127
    const int le = (tid & 1) * 16;         // element offset within BK (0 or 16)
    const uint32_t lso = (uint32_t)lr * PITCH + (tid & 1) * 32;   // smem byte offset in matrix

    auto load_stage = [&](int ck, int s) {
        const int k0 = (ck << 5) + le;
        const uint32_t st = sb + (uint32_t)s * STAGE_B + lso;
        const size_t ao = (size_t)(m0 + lr) * lda + k0;
        const size_t bo = (size_t)(n0 + lr) * ldb + k0;
        CP16(st +                 0, Ahi + ao); CP16(st +                 16, Ahi + ao + 8);
        CP16(st +     MAT_BYTES + 0, Alo + ao); CP16(st +     MAT_BYTES + 16, Alo + ao + 8);
        CP16(st + 2 * MAT_BYTES + 0, Bhi + bo); CP16(st + 2 * MAT_BYTES + 16, Bhi + bo + 8);
        CP16(st + 3 * MAT_BYTES + 0, Blo + bo); CP16(st + 3 * MAT_BYTES + 16, Blo + bo + 8);
    };

    load_stage(0, 0); CP_COMMIT();
    load_stage(1, 1); CP_COMMIT();

    // ---- fragment lane addressing (constant across iterations)
    const uint32_t a_off = (uint32_t)(wm + (lane & 15)) * PITCH + (lane >> 4) * 16;
    const uint32_t b_off = 2 * MAT_BYTES + (uint32_t)(wn + (lane & 7)) * PITCH + ((lane >> 3) & 1) * 16;

    for (int i = 0; i < NC; i++) {
        CP_WAIT1();
        __syncthreads();
        if (i + 2 < NC) load_stage(i + 2, (i + 2) % 3);
        CP_COMMIT();

        const uint32_t st = sb + (uint32_t)(i % 3) * STAGE_B;
#pragma unroll
        for (int ks = 0; ks < 2; ks++) {
            const uint32_t kb = ks * 32;   // 16 bf16 = 32 bytes
            uint32_t a0f[4][4], a1f[4][4], b0f[4][2], b1f[4][2];
#pragma unroll
            for (int mt = 0; mt < 4; mt++) {
                const uint32_t ad = st + a_off + (uint32_t)mt * (16 * PITCH) + kb;
                LDSM4(a0f[mt], ad);
                LDSM4(a1f[mt], ad + MAT_BYTES);
            }
#pragma unroll
            for (int nt = 0; nt < 4; nt++) {
                const uint32_t bd = st + b_off + (uint32_t)nt * (8 * PITCH) + kb;
                LDSM2(b0f[nt], bd);
                LDSM2(b1f[nt], bd + MAT_BYTES);
            }
#pragma unroll
            for (int mt = 0; mt < 4; mt++)
#pragma unroll
                for (int nt = 0; nt < 4; nt++) {
                    MMA16816(acc[mt * 4 + nt], a0f[mt], b0f[nt]);
                    MMA16816(acc[mt * 4 + nt], a0f[mt], b1f[nt]);
                    MMA16816(acc[mt * 4 + nt], a1f[mt], b0f[nt]);
                }
        }
    }

    // ---- epilogue
    const int rowg = lane >> 2;            // 0..7
    const int colp = (lane & 3) * 2;
#pragma unroll
    for (int mt = 0; mt < 4; mt++) {
#pragma unroll
        for (int nt = 0; nt < 4; nt++) {
            const int col = n0 + wn + nt * 8 + colp;
            const int r0 = m0 + wm + mt * 16 + rowg;
            const int r1 = r0 + 8;
            float* __restrict__ acc4 = acc[mt * 4 + nt];
            float2 v0 = make_float2(acc4[0], acc4[1]);
            float2 v1 = make_float2(acc4[2], acc4[3]);
            if (EPI) {
                const float2 q0 = *(const float2*)(R + (size_t)r0 * ldc + col);
                const float2 q1 = *(const float2*)(R + (size_t)r1 * ldc + col);
                v0.x = lrelu(v0.x + q0.x); v0.y = lrelu(v0.y + q0.y);
                v1.x = lrelu(v1.x + q1.x); v1.y = lrelu(v1.y + q1.y);
            }
            *(float2*)(C + (size_t)r0 * ldc + col) = v0;
            *(float2*)(C + (size_t)r1 * ldc + col) = v1;
        }
    }
}

// ---------------------------------------------------------------------------
// Row softmax * adj, output split into bf16 hi/lo.
// ---------------------------------------------------------------------------
__global__ void __launch_bounds__(256)
softmax_mask_split(const float* __restrict__ S, const float* __restrict__ adj,
                   __nv_bfloat16* __restrict__ Phi, __nv_bfloat16* __restrict__ Plo)
{
    __shared__ float row[NN];
    __shared__ float red[256];
    const int tid = threadIdx.x;
    const size_t base = (size_t)blockIdx.x * NN;

    for (int j = tid * 4; j < NN; j += 1024)
        *(float4*)&row[j] = *(const float4*)&S[base + j];
    __syncthreads();

    float m = -INFINITY;
    for (int j = tid; j < NN; j += 256) m = fmaxf(m, row[j]);
    red[tid] = m; __syncthreads();
    for (int s = 128; s > 0; s >>= 1) { if (tid < s) red[tid] = fmaxf(red[tid], red[tid + s]); __syncthreads(); }
    m = red[0]; __syncthreads();

    float l = 0.f;
    for (int j = tid; j < NN; j += 256) l += __expf(row[j] - m);
    red[tid] = l; __syncthreads();
    for (int s = 128; s > 0; s >>= 1) { if (tid < s) red[tid] += red[tid + s]; __syncthreads(); }
    const float inv = 1.0f / red[0];

    for (int j = tid * 4; j < NN; j += 1024) {
        float4 a = *(const float4*)&adj[base + j];
        float p0 = __expf(row[j + 0] - m) * inv * a.x;
        float p1 = __expf(row[j + 1] - m) * inv * a.y;
        float p2 = __expf(row[j + 2] - m) * inv * a.z;
        float p3 = __expf(row[j + 3] - m) * inv * a.w;
        __nv_bfloat16 h0 = __float2bfloat16_rn(p0), h1 = __float2bfloat16_rn(p1);
        __nv_bfloat16 h2 = __float2bfloat16_rn(p2), h3 = __float2bfloat16_rn(p3);
        __nv_bfloat16 l0 = __float2bfloat16_rn(p0 - __bfloat162float(h0));
        __nv_bfloat16 l1 = __float2bfloat16_rn(p1 - __bfloat162float(h1));
        __nv_bfloat16 l2 = __float2bfloat16_rn(p2 - __bfloat162float(h2));
        __nv_bfloat16 l3 = __float2bfloat16_rn(p3 - __bfloat162float(h3));
        __nv_bfloat162* ph = (__nv_bfloat162*)(Phi + base + j);
        __nv_bfloat162* pl = (__nv_bfloat162*)(Plo + base + j);
        ph[0] = __nv_bfloat162(h0, h1); ph[1] = __nv_bfloat162(h2, h3);
        pl[0] = __nv_bfloat162(l0, l1); pl[1] = __nv_bfloat162(l2, l3);
    }
}

// ---------------------------------------------------------------------------
// fp32 -> bf16 hi/lo split (elementwise)
// ---------------------------------------------------------------------------
__global__ void __launch_bounds__(256)
convert_split(const float* __restrict__ in, __nv_bfloat16* __restrict__ hi,
              __nv_bfloat16* __restrict__ lo, int n4)
{
    int i = blockIdx.x * blockDim.x + threadIdx.x;
    if (i >= n4) return;
    float4 x = ((const float4*)in)[i];
    __nv_bfloat16 h0 = __float2bfloat16_rn(x.x), h1 = __float2bfloat16_rn(x.y);
    __nv_bfloat16 h2 = __float2bfloat16_rn(x.z), h3 = __float2bfloat16_rn(x.w);
    __nv_bfloat162* ph = (__nv_bfloat162*)(hi) + i * 2;
    __nv_bfloat162* pl = (__nv_bfloat162*)(lo) + i * 2;
    ph[0] = __nv_bfloat162(h0, h1); ph[1] = __nv_bfloat162(h2, h3);
    pl[0] = __nv_bfloat162(__float2bfloat16_rn(x.x - __bfloat162float(h0)),
                           __float2bfloat16_rn(x.y - __bfloat162float(h1)));
    pl[1] = __nv_bfloat162(__float2bfloat16_rn(x.z - __bfloat162float(h2)),
                           __float2bfloat16_rn(x.w - __bfloat162float(h3)));
}

// ---------------------------------------------------------------------------
// split proj [8192,1024] into Wh (cols 0..511) and Ws (cols 512..1023) bf16 pairs
// ---------------------------------------------------------------------------
__global__ void __launch_bounds__(256)
proj_split(const float* __restrict__ proj,
           __nv_bfloat16* __restrict__ WhHi, __nv_bfloat16* __restrict__ WhLo,
           __nv_bfloat16* __restrict__ WsHi, __nv_bfloat16* __restrict__ WsLo)
{
    int i = blockIdx.x * blockDim.x + threadIdx.x;   // over NN*1024/4
    int rowi = i >> 8;
    int col4 = (i & 255) << 2;
    float4 x = ((const float4*)proj)[i];
    __nv_bfloat16* hi; __nv_bfloat16* lo; int off;
    if (col4 < DD) { hi = WhHi; lo = WhLo; off = rowi * DD + col4; }
    else           { hi = WsHi; lo = WsLo; off = rowi * DD + col4 - DD; }
    __nv_bfloat16 h0 = __float2bfloat16_rn(x.x), h1 = __float2bfloat16_rn(x.y);
    __nv_bfloat16 h2 = __float2bfloat16_rn(x.z), h3 = __float2bfloat16_rn(x.w);
    __nv_bfloat162* ph = (__nv_bfloat162*)(hi + off);
    __nv_bfloat162* pl = (__nv_bfloat162*)(lo + off);
    ph[0] = __nv_bfloat162(h0, h1); ph[1] = __nv_bfloat162(h2, h3);
    pl[0] = __nv_bfloat162(__float2bfloat16_rn(x.x - __bfloat162float(h0)),
                           __float2bfloat16_rn(x.y - __bfloat162float(h1)));
    pl[1] = __nv_bfloat162(__float2bfloat16_rn(x.z - __bfloat162float(h2)),
                           __float2bfloat16_rn(x.w - __bfloat162float(h3)));
}

// ---------------------------------------------------------------------------
// transpose fp32 [R,C](ldin) -> bf16 hi/lo [C,R](ldout)
// ---------------------------------------------------------------------------
__global__ void __launch_bounds__(256)
transpose_split(const float* __restrict__ in, int ldin,
                __nv_bfloat16* __restrict__ hi, __nv_bfloat16* __restrict__ lo, int ldout)
{
    __shared__ float t[32][33];
    const int tx = threadIdx.x, ty = threadIdx.y;
    const int c0 = blockIdx.x * 32, r0 = blockIdx.y * 32;
#pragma unroll
    for (int k = 0; k < 4; k++)
        t[ty + 8 * k][tx] = in[(size_t)(r0 + ty + 8 * k) * ldin + c0 + tx];
    __syncthreads();
#pragma unroll
    for (int k = 0; k < 4; k++) {
        float v = t[tx][ty + 8 * k];
        __nv_bfloat16 h = __float2bfloat16_rn(v);
        size_t o = (size_t)(c0 + ty + 8 * k) * ldout + r0 + tx;
        hi[o] = h;
        lo[o] = __float2bfloat16_rn(v - __bfloat162float(h));
    }
}

// ---------------------------------------------------------------------------
extern "C" void kernel_launch(void* const* d_in, const int* in_sizes, int n_in,
                              void* d_out, int out_size)
{
    const float* x0 = nullptr; const float* adj = nullptr; const float* W = nullptr;
    for (int i = 0; i < n_in; i++) {
        const int s = in_sizes[i];
        if      (s == NN * DD)           x0  = (const float*)d_in[i];
        else if (s == 67108864)          adj = (const float*)d_in[i];
        else if (s == NL * DD * 2 * DD)  W   = (const float*)d_in[i];
    }

    cudaFuncSetAttribute((const void*)gemm_mma<false>, cudaFuncAttributeMaxDynamicSharedMemorySize, GEMM_SMEM);
    cudaFuncSetAttribute((const void*)gemm_mma<true>,  cudaFuncAttributeMaxDynamicSharedMemorySize, GEMM_SMEM);

    float *S, *proj, *Xf;
    __nv_bfloat16 *Phi, *Plo, *Whhi, *Whlo, *Wshi, *Wslo, *WhThi, *WhTlo, *Xhi, *Xlo, *Wthi, *Wtlo;
    cudaGetSymbolAddress((void**)&S, g_S);       cudaGetSymbolAddress((void**)&proj, g_proj);
    cudaGetSymbolAddress((void**)&Xf, g_Xf);
    cudaGetSymbolAddress((void**)&Phi, g_Phi);   cudaGetSymbolAddress((void**)&Plo, g_Plo);
    cudaGetSymbolAddress((void**)&Whhi, g_Whhi); cudaGetSymbolAddress((void**)&Whlo, g_Whlo);
    cudaGetSymbolAddress((void**)&Wshi, g_Wshi); cudaGetSymbolAddress((void**)&Wslo, g_Wslo);
    cudaGetSymbolAddress((void**)&WhThi, g_WhThi); cudaGetSymbolAddress((void**)&WhTlo, g_WhTlo);
    cudaGetSymbolAddress((void**)&Xhi, g_Xhi);   cudaGetSymbolAddress((void**)&Xlo, g_Xlo);
    cudaGetSymbolAddress((void**)&Wthi, g_Wthi); cudaGetSymbolAddress((void**)&Wtlo, g_Wtlo);

    const dim3 blk(256);
    const dim3 tblk(32, 8);

    // W^T per layer: [512,1024] -> [1024,512] bf16 pairs
    for (int l = 0; l < NL; l++)
        transpose_split<<<dim3(2 * DD / 32, DD / 32), tblk>>>(W + (size_t)l * DD * 2 * DD, 2 * DD,
                                                              Wthi + (size_t)l * 2 * DD * DD,
                                                              Wtlo + (size_t)l * 2 * DD * DD, DD);
    // x0 split
    convert_split<<<(NN * DD / 4 + 255) / 256, blk>>>(x0, Xhi, Xlo, NN * DD / 4);

    const float* xin = x0;
    for (int l = 0; l < NL; l++) {
        const __nv_bfloat16* wthi = Wthi + (size_t)l * 2 * DD * DD;
        const __nv_bfloat16* wtlo = Wtlo + (size_t)l * 2 * DD * DD;

        // proj = x @ W_l   -> [8192, 1024] fp32
        gemm_mma<false><<<dim3(2 * DD / 128, NN / 128), blk, GEMM_SMEM>>>(
            Xhi, Xlo, DD, wthi, wtlo, DD, proj, 2 * DD, nullptr, DD);

        // split proj into Wh/Ws bf16 pairs
        proj_split<<<NN * 2 * DD / 4 / 256, blk>>>(proj, Whhi, Whlo, Wshi, Wslo);
        // WhT = transpose(proj[:, :512]) -> [512, 8192] bf16 pairs
        transpose_split<<<dim3(DD / 32, NN / 32), tblk>>>(proj, 2 * DD, WhThi, WhTlo, NN);

        // S = Wh @ Ws^T
        gemm_mma<false><<<dim3(NN / 128, NN / 128), blk, GEMM_SMEM>>>(
            Whhi, Whlo, DD, Wshi, Wslo, DD, S, NN, nullptr, DD);

        // P = softmax(S) * adj  -> bf16 pairs
        softmax_mask_split<<<NN, blk>>>(S, adj, Phi, Plo);

        // out = leaky_relu(P @ Wh + xin)
        float* outp = (l == NL - 1) ? (float*)d_out : Xf;
        gemm_mma<true><<<dim3(DD / 128, NN / 128), blk, GEMM_SMEM>>>(
            Phi, Plo, NN, WhThi, WhTlo, NN, outp, DD, xin, NN);

        if (l == 0) {
            convert_split<<<(NN * DD / 4 + 255) / 256, blk>>>(Xf, Xhi, Xlo, NN * DD / 4);
            xin = Xf;
        }
    }
}

// round 5
// speedup vs baseline: 2.3620x; 1.1328x over previous
#include <cuda_runtime.h>
#include <cuda_bf16.h>
#include <math.h>
#include <stdint.h>

#define NN 8192
#define DD 512
#define NL 2

// ---------------- device scratch (no allocations allowed) ----------------
__device__ float          g_S   [(size_t)NN * NN];        // 256 MB scores
__device__ __nv_bfloat16  g_Phi [(size_t)NN * NN];        // 128 MB
__device__ __nv_bfloat16  g_Plo [(size_t)NN * NN];        // 128 MB
__device__ float          g_proj[(size_t)NN * 2 * DD];    // 32 MB
__device__ float          g_Xf  [(size_t)NN * DD];        // 16 MB layer-0 output
__device__ __nv_bfloat16  g_Whhi[NN * DD], g_Whlo[NN * DD];
__device__ __nv_bfloat16  g_Wshi[NN * DD], g_Wslo[NN * DD];
__device__ __nv_bfloat16  g_WhThi[NN * DD], g_WhTlo[NN * DD];   // [512, 8192]
__device__ __nv_bfloat16  g_Xhi [NN * DD], g_Xlo [NN * DD];
__device__ __nv_bfloat16  g_Wthi[NL * 2 * DD * DD], g_Wtlo[NL * 2 * DD * DD]; // [L,1024,512]

// ---------------- PTX helpers (sm_80+ baseline only) ----------------
__device__ __forceinline__ uint32_t smem_u32(const void* p) {
    uint32_t a;
    asm("{ .reg .u64 t; cvta.to.shared.u64 t, %1; cvt.u32.u64 %0, t; }" : "=r"(a) : "l"(p));
    return a;
}
#define CP16(dst, src)  asm volatile("cp.async.cg.shared.global [%0], [%1], 16;" :: "r"(dst), "l"(src))
#define CP_COMMIT()     asm volatile("cp.async.commit_group;" ::: "memory")
#define CP_WAIT1()      asm volatile("cp.async.wait_group 1;" ::: "memory")

#define LDSM4(r, a) \
    asm volatile("ldmatrix.sync.aligned.m8n8.x4.shared.b16 {%0,%1,%2,%3}, [%4];" \
        : "=r"((r)[0]), "=r"((r)[1]), "=r"((r)[2]), "=r"((r)[3]) : "r"(a))

#define MMA16816(c, a, b) \
    asm volatile("mma.sync.aligned.m16n8k16.row.col.f32.bf16.bf16.f32 " \
        "{%0,%1,%2,%3}, {%4,%5,%6,%7}, {%8,%9}, {%0,%1,%2,%3};" \
        : "+f"((c)[0]), "+f"((c)[1]), "+f"((c)[2]), "+f"((c)[3]) \
        : "r"((a)[0]), "r"((a)[1]), "r"((a)[2]), "r"((a)[3]), "r"((b)[0]), "r"((b)[1]))

__device__ __forceinline__ float lrelu(float v) { return v > 0.f ? v : 0.01f * v; }

// ---------------------------------------------------------------------------
// bf16-split GEMM on HMMA (mma.sync m16n8k16):
//   C[M,N] = sum_K (Ahi+Alo)[M,K] * (Bhi+Blo)[N,K]^T   (3 terms: A0B0+A0B1+A1B0)
// BM=BN=128, BK=32. 8 warps (2x4), warp tile 64x32. 2-stage cp.async pipeline,
// 2 CTAs/SM (81920 B smem each). EPI: C = leaky_relu(C + R).
// ---------------------------------------------------------------------------
#define PITCH      80
#define MAT_BYTES  (128 * PITCH)       // 10240
#define STAGE_B    (4 * MAT_BYTES)     // 40960
#define GEMM_SMEM  (2 * STAGE_B)       // 81920

template<bool EPI>
__global__ void __launch_bounds__(256, 2)
gemm_mma(const __nv_bfloat16* __restrict__ Ahi, const __nv_bfloat16* __restrict__ Alo, int lda,
         const __nv_bfloat16* __restrict__ Bhi, const __nv_bfloat16* __restrict__ Blo, int ldb,
         float* __restrict__ C, int ldc, const float* __restrict__ R, int K)
{
    extern __shared__ char smem[];
    const uint32_t sb = smem_u32(smem);
    const int tid = threadIdx.x, wid = tid >> 5, lane = tid & 31;
    const int m0 = blockIdx.y * 128, n0 = blockIdx.x * 128;
    const int wm = (wid & 1) * 64;       // warp M offset
    const int wn = (wid >> 1) * 32;      // warp N offset
    const int NC = K >> 5;               // number of BK=32 chunks

    float acc[16][4];
#pragma unroll
    for (int i = 0; i < 16; i++)
#pragma unroll
        for (int q = 0; q < 4; q++) acc[i][q] = 0.f;

    // ---- load geometry: per matrix 512 x 16B chunks; thread loads 32B of one row
    const int lr = tid >> 1;               // row 0..127
    const int le = (tid & 1) * 16;         // element offset within BK (0 or 16)
    const uint32_t lso = (uint32_t)lr * PITCH + (tid & 1) * 32;

    auto load_stage = [&](int ck, int s) {
        const int k0 = (ck << 5) + le;
        const uint32_t st = sb + (uint32_t)s * STAGE_B + lso;
        const size_t ao = (size_t)(m0 + lr) * lda + k0;
        const size_t bo = (size_t)(n0 + lr) * ldb + k0;
        CP16(st +                 0, Ahi + ao); CP16(st +                 16, Ahi + ao + 8);
        CP16(st +     MAT_BYTES + 0, Alo + ao); CP16(st +     MAT_BYTES + 16, Alo + ao + 8);
        CP16(st + 2 * MAT_BYTES + 0, Bhi + bo); CP16(st + 2 * MAT_BYTES + 16, Bhi + bo + 8);
        CP16(st + 3 * MAT_BYTES + 0, Blo + bo); CP16(st + 3 * MAT_BYTES + 16, Blo + bo + 8);
    };

    // ---- fragment lane addressing (constant across iterations)
    // A: ldmatrix x4 over 16 rows, two 16B k-columns
    const uint32_t a_off = (uint32_t)(wm + (lane & 15)) * PITCH + (lane >> 4) * 16;
    // B: ldmatrix x4 covering TWO n8 tiles: {r0,r1}=even-nt {k-lo,k-hi}, {r2,r3}=odd-nt
    const uint32_t b_off = 2 * MAT_BYTES
        + (uint32_t)(wn + (lane & 7) + ((lane >> 4) & 1) * 8) * PITCH
        + ((lane >> 3) & 1) * 16;

    load_stage(0, 0); CP_COMMIT();

    for (int i = 0; i < NC; i++) {
        if (i + 1 < NC) load_stage(i + 1, (i + 1) & 1);
        CP_COMMIT();
        CP_WAIT1();
        __syncthreads();                    // stage i data visible to all warps

        const uint32_t st = sb + (uint32_t)(i & 1) * STAGE_B;
#pragma unroll
        for (int ks = 0; ks < 2; ks++) {
            const uint32_t kb = ks * 32;    // 16 bf16 = 32 bytes
            uint32_t b0f[2][4], b1f[2][4];  // [ntPair][4 regs]
#pragma unroll
            for (int p = 0; p < 2; p++) {
                const uint32_t bd = st + b_off + (uint32_t)p * (16 * PITCH) + kb;
                LDSM4(b0f[p], bd);
                LDSM4(b1f[p], bd + MAT_BYTES);
            }
#pragma unroll
            for (int mt = 0; mt < 4; mt++) {
                const uint32_t ad = st + a_off + (uint32_t)mt * (16 * PITCH) + kb;
                uint32_t a0f[4], a1f[4];
                LDSM4(a0f, ad);
                LDSM4(a1f, ad + MAT_BYTES);
#pragma unroll
                for (int nt = 0; nt < 4; nt++) {
                    const int bp = nt >> 1, q = (nt & 1) * 2;
                    MMA16816(acc[mt * 4 + nt], a0f, &b0f[bp][q]);
                    MMA16816(acc[mt * 4 + nt], a0f, &b1f[bp][q]);
                    MMA16816(acc[mt * 4 + nt], a1f, &b0f[bp][q]);
                }
            }
        }
        __syncthreads();                    // all warps done with stage i before overwrite
    }

    // ---- epilogue
    const int rowg = lane >> 2;
    const int colp = (lane & 3) * 2;
#pragma unroll
    for (int mt = 0; mt < 4; mt++) {
#pragma unroll
        for (int nt = 0; nt < 4; nt++) {
            const int col = n0 + wn + nt * 8 + colp;
            const int r0 = m0 + wm + mt * 16 + rowg;
            const int r1 = r0 + 8;
            float* __restrict__ acc4 = acc[mt * 4 + nt];
            float2 v0 = make_float2(acc4[0], acc4[1]);
            float2 v1 = make_float2(acc4[2], acc4[3]);
            if (EPI) {
                const float2 q0 = *(const float2*)(R + (size_t)r0 * ldc + col);
                const float2 q1 = *(const float2*)(R + (size_t)r1 * ldc + col);
                v0.x = lrelu(v0.x + q0.x); v0.y = lrelu(v0.y + q0.y);
                v1.x = lrelu(v1.x + q1.x); v1.y = lrelu(v1.y + q1.y);
            }
            *(float2*)(C + (size_t)r0 * ldc + col) = v0;
            *(float2*)(C + (size_t)r1 * ldc + col) = v1;
        }
    }
}

// ---------------------------------------------------------------------------
// Row softmax * adj, output split into bf16 hi/lo.
// ---------------------------------------------------------------------------
__global__ void __launch_bounds__(256)
softmax_mask_split(const float* __restrict__ S, const float* __restrict__ adj,
                   __nv_bfloat16* __restrict__ Phi, __nv_bfloat16* __restrict__ Plo)
{
    __shared__ float row[NN];
    __shared__ float red[256];
    const int tid = threadIdx.x;
    const size_t base = (size_t)blockIdx.x * NN;

    for (int j = tid * 4; j < NN; j += 1024)
        *(float4*)&row[j] = *(const float4*)&S[base + j];
    __syncthreads();

    float m = -INFINITY;
    for (int j = tid; j < NN; j += 256) m = fmaxf(m, row[j]);
    red[tid] = m; __syncthreads();
    for (int s = 128; s > 0; s >>= 1) { if (tid < s) red[tid] = fmaxf(red[tid], red[tid + s]); __syncthreads(); }
    m = red[0]; __syncthreads();

    float l = 0.f;
    for (int j = tid; j < NN; j += 256) l += __expf(row[j] - m);
    red[tid] = l; __syncthreads();
    for (int s = 128; s > 0; s >>= 1) { if (tid < s) red[tid] += red[tid + s]; __syncthreads(); }
    const float inv = 1.0f / red[0];

    for (int j = tid * 4; j < NN; j += 1024) {
        float4 a = *(const float4*)&adj[base + j];
        float p0 = __expf(row[j + 0] - m) * inv * a.x;
        float p1 = __expf(row[j + 1] - m) * inv * a.y;
        float p2 = __expf(row[j + 2] - m) * inv * a.z;
        float p3 = __expf(row[j + 3] - m) * inv * a.w;
        __nv_bfloat16 h0 = __float2bfloat16_rn(p0), h1 = __float2bfloat16_rn(p1);
        __nv_bfloat16 h2 = __float2bfloat16_rn(p2), h3 = __float2bfloat16_rn(p3);
        __nv_bfloat16 l0 = __float2bfloat16_rn(p0 - __bfloat162float(h0));
        __nv_bfloat16 l1 = __float2bfloat16_rn(p1 - __bfloat162float(h1));
        __nv_bfloat16 l2 = __float2bfloat16_rn(p2 - __bfloat162float(h2));
        __nv_bfloat16 l3 = __float2bfloat16_rn(p3 - __bfloat162float(h3));
        __nv_bfloat162* ph = (__nv_bfloat162*)(Phi + base + j);
        __nv_bfloat162* pl = (__nv_bfloat162*)(Plo + base + j);
        ph[0] = __nv_bfloat162(h0, h1); ph[1] = __nv_bfloat162(h2, h3);
        pl[0] = __nv_bfloat162(l0, l1); pl[1] = __nv_bfloat162(l2, l3);
    }
}

// ---------------------------------------------------------------------------
// fp32 -> bf16 hi/lo split (elementwise)
// ---------------------------------------------------------------------------
__global__ void __launch_bounds__(256)
convert_split(const float* __restrict__ in, __nv_bfloat16* __restrict__ hi,
              __nv_bfloat16* __restrict__ lo, int n4)
{
    int i = blockIdx.x * blockDim.x + threadIdx.x;
    if (i >= n4) return;
    float4 x = ((const float4*)in)[i];
    __nv_bfloat16 h0 = __float2bfloat16_rn(x.x), h1 = __float2bfloat16_rn(x.y);
    __nv_bfloat16 h2 = __float2bfloat16_rn(x.z), h3 = __float2bfloat16_rn(x.w);
    __nv_bfloat162* ph = (__nv_bfloat162*)(hi) + i * 2;
    __nv_bfloat162* pl = (__nv_bfloat162*)(lo) + i * 2;
    ph[0] = __nv_bfloat162(h0, h1); ph[1] = __nv_bfloat162(h2, h3);
    pl[0] = __nv_bfloat162(__float2bfloat16_rn(x.x - __bfloat162float(h0)),
                           __float2bfloat16_rn(x.y - __bfloat162float(h1)));
    pl[1] = __nv_bfloat162(__float2bfloat16_rn(x.z - __bfloat162float(h2)),
                           __float2bfloat16_rn(x.w - __bfloat162float(h3)));
}

// ---------------------------------------------------------------------------
// split proj [8192,1024] into Wh (cols 0..511) and Ws (cols 512..1023) bf16 pairs
// ---------------------------------------------------------------------------
__global__ void __launch_bounds__(256)
proj_split(const float* __restrict__ proj,
           __nv_bfloat16* __restrict__ WhHi, __nv_bfloat16* __restrict__ WhLo,
           __nv_bfloat16* __restrict__ WsHi, __nv_bfloat16* __restrict__ WsLo)
{
    int i = blockIdx.x * blockDim.x + threadIdx.x;   // over NN*1024/4
    int rowi = i >> 8;
    int col4 = (i & 255) << 2;
    float4 x = ((const float4*)proj)[i];
    __nv_bfloat16* hi; __nv_bfloat16* lo; int off;
    if (col4 < DD) { hi = WhHi; lo = WhLo; off = rowi * DD + col4; }
    else           { hi = WsHi; lo = WsLo; off = rowi * DD + col4 - DD; }
    __nv_bfloat16 h0 = __float2bfloat16_rn(x.x), h1 = __float2bfloat16_rn(x.y);
    __nv_bfloat16 h2 = __float2bfloat16_rn(x.z), h3 = __float2bfloat16_rn(x.w);
    __nv_bfloat162* ph = (__nv_bfloat162*)(hi + off);
    __nv_bfloat162* pl = (__nv_bfloat162*)(lo + off);
    ph[0] = __nv_bfloat162(h0, h1); ph[1] = __nv_bfloat162(h2, h3);
    pl[0] = __nv_bfloat162(__float2bfloat16_rn(x.x - __bfloat162float(h0)),
                           __float2bfloat16_rn(x.y - __bfloat162float(h1)));
    pl[1] = __nv_bfloat162(__float2bfloat16_rn(x.z - __bfloat162float(h2)),
                           __float2bfloat16_rn(x.w - __bfloat162float(h3)));
}

// ---------------------------------------------------------------------------
// transpose fp32 [R,C](ldin) -> bf16 hi/lo [C,R](ldout)
// ---------------------------------------------------------------------------
__global__ void __launch_bounds__(256)
transpose_split(const float* __restrict__ in, int ldin,
                __nv_bfloat16* __restrict__ hi, __nv_bfloat16* __restrict__ lo, int ldout)
{
    __shared__ float t[32][33];
    const int tx = threadIdx.x, ty = threadIdx.y;
    const int c0 = blockIdx.x * 32, r0 = blockIdx.y * 32;
#pragma unroll
    for (int k = 0; k < 4; k++)
        t[ty + 8 * k][tx] = in[(size_t)(r0 + ty + 8 * k) * ldin + c0 + tx];
    __syncthreads();
#pragma unroll
    for (int k = 0; k < 4; k++) {
        float v = t[tx][ty + 8 * k];
        __nv_bfloat16 h = __float2bfloat16_rn(v);
        size_t o = (size_t)(c0 + ty + 8 * k) * ldout + r0 + tx;
        hi[o] = h;
        lo[o] = __float2bfloat16_rn(v - __bfloat162float(h));
    }
}

// ---------------------------------------------------------------------------
extern "C" void kernel_launch(void* const* d_in, const int* in_sizes, int n_in,
                              void* d_out, int out_size)
{
    const float* x0 = nullptr; const float* adj = nullptr; const float* W = nullptr;
    for (int i = 0; i < n_in; i++) {
        const int s = in_sizes[i];
        if      (s == NN * DD)           x0  = (const float*)d_in[i];
        else if (s == 67108864)          adj = (const float*)d_in[i];
        else if (s == NL * DD * 2 * DD)  W   = (const float*)d_in[i];
    }

    cudaFuncSetAttribute((const void*)gemm_mma<false>, cudaFuncAttributeMaxDynamicSharedMemorySize, GEMM_SMEM);
    cudaFuncSetAttribute((const void*)gemm_mma<true>,  cudaFuncAttributeMaxDynamicSharedMemorySize, GEMM_SMEM);

    float *S, *proj, *Xf;
    __nv_bfloat16 *Phi, *Plo, *Whhi, *Whlo, *Wshi, *Wslo, *WhThi, *WhTlo, *Xhi, *Xlo, *Wthi, *Wtlo;
    cudaGetSymbolAddress((void**)&S, g_S);       cudaGetSymbolAddress((void**)&proj, g_proj);
    cudaGetSymbolAddress((void**)&Xf, g_Xf);
    cudaGetSymbolAddress((void**)&Phi, g_Phi);   cudaGetSymbolAddress((void**)&Plo, g_Plo);
    cudaGetSymbolAddress((void**)&Whhi, g_Whhi); cudaGetSymbolAddress((void**)&Whlo, g_Whlo);
    cudaGetSymbolAddress((void**)&Wshi, g_Wshi); cudaGetSymbolAddress((void**)&Wslo, g_Wslo);
    cudaGetSymbolAddress((void**)&WhThi, g_WhThi); cudaGetSymbolAddress((void**)&WhTlo, g_WhTlo);
    cudaGetSymbolAddress((void**)&Xhi, g_Xhi);   cudaGetSymbolAddress((void**)&Xlo, g_Xlo);
    cudaGetSymbolAddress((void**)&Wthi, g_Wthi); cudaGetSymbolAddress((void**)&Wtlo, g_Wtlo);

    const dim3 blk(256);
    const dim3 tblk(32, 8);

    // W^T per layer: [512,1024] -> [1024,512] bf16 pairs
    for (int l = 0; l < NL; l++)
        transpose_split<<<dim3(2 * DD / 32, DD / 32), tblk>>>(W + (size_t)l * DD * 2 * DD, 2 * DD,
                                                              Wthi + (size_t)l * 2 * DD * DD,
                                                              Wtlo + (size_t)l * 2 * DD * DD, DD);
    // x0 split
    convert_split<<<(NN * DD / 4 + 255) / 256, blk>>>(x0, Xhi, Xlo, NN * DD / 4);

    const float* xin = x0;
    for (int l = 0; l < NL; l++) {
        const __nv_bfloat16* wthi = Wthi + (size_t)l * 2 * DD * DD;
        const __nv_bfloat16* wtlo = Wtlo + (size_t)l * 2 * DD * DD;

        // proj = x @ W_l   -> [8192, 1024] fp32
        gemm_mma<false><<<dim3(2 * DD / 128, NN / 128), blk, GEMM_SMEM>>>(
            Xhi, Xlo, DD, wthi, wtlo, DD, proj, 2 * DD, nullptr, DD);

        // split proj into Wh/Ws bf16 pairs
        proj_split<<<NN * 2 * DD / 4 / 256, blk>>>(proj, Whhi, Whlo, Wshi, Wslo);
        // WhT = transpose(proj[:, :512]) -> [512, 8192] bf16 pairs
        transpose_split<<<dim3(DD / 32, NN / 32), tblk>>>(proj, 2 * DD, WhThi, WhTlo, NN);

        // S = Wh @ Ws^T
        gemm_mma<false><<<dim3(NN / 128, NN / 128), blk, GEMM_SMEM>>>(
            Whhi, Whlo, DD, Wshi, Wslo, DD, S, NN, nullptr, DD);

        // P = softmax(S) * adj  -> bf16 pairs
        softmax_mask_split<<<NN, blk>>>(S, adj, Phi, Plo);

        // out = leaky_relu(P @ Wh + xin)
        float* outp = (l == NL - 1) ? (float*)d_out : Xf;
        gemm_mma<true><<<dim3(DD / 128, NN / 128), blk, GEMM_SMEM>>>(
            Phi, Plo, NN, WhThi, WhTlo, NN, outp, DD, xin, NN);

        if (l == 0) {
            convert_split<<<(NN * DD / 4 + 255) / 256, blk>>>(Xf, Xhi, Xlo, NN * DD / 4);
            xin = Xf;
        }
    }
}